// round 13
// baseline (speedup 1.0000x reference)
#include <cuda_runtime.h>
#include <cuda_fp16.h>
#include <math.h>
#include <stdint.h>

#define HID  1024
#define FFN  4096
#define NE   8
#define NTOK 4096
#define ECAP 1536                      // fixed rows per expert segment (18-sigma safe)
#define CAPR (NE * ECAP)               // 12288 total rows

#define BM 128
#define BN 128
#define BK 32
#define STAGES 4
#define THREADS 256                    // 8 warps, 64x32 warp tiles (2x4)
#define APAD 40                        // halves per A smem row (80 B, conflict-free LDSM)
#define BPAD 136                       // halves per B smem k-row (272 B, conflict-free LDSM)
#define ABYTES (BM * APAD * 2)         // 10240
#define BBYTES (BK * BPAD * 2)         // 8704
#define STGB   (ABYTES + BBYTES)       // 18944
#define SMEM_TOTAL (STAGES * STGB)     // 75776 -> 2 CTAs/SM (151.5 KB)

// ---------------- scratch (device globals; zero-initialized at load) ----------------
__device__ int    g_cnt[NE];
__device__ int    g_rowTok[CAPR];
__device__ float  g_rowW[CAPR];
__device__ __half g_Xh[(size_t)CAPR * HID];
__device__ __half g_Hh[(size_t)CAPR * FFN];
__device__ __half g_W1h[(size_t)NE * HID * FFN];
__device__ __half g_W2h[(size_t)NE * FFN * HID];

// ---------------- helpers ----------------
__device__ __forceinline__ uint32_t smem_u32(const void* p) {
    uint32_t a;
    asm("{ .reg .u64 t; cvta.to.shared.u64 t, %1; cvt.u32.u64 %0, t; }" : "=r"(a) : "l"(p));
    return a;
}
__device__ __forceinline__ void cpa16(uint32_t s, const void* g) {
    asm volatile("cp.async.cg.shared.global [%0], [%1], 16;\n" :: "r"(s), "l"(g));
}
__device__ __forceinline__ void ldsm4(unsigned* r, uint32_t a) {
    asm volatile("ldmatrix.sync.aligned.m8n8.x4.shared.b16 {%0,%1,%2,%3}, [%4];"
                 : "=r"(r[0]), "=r"(r[1]), "=r"(r[2]), "=r"(r[3]) : "r"(a));
}
__device__ __forceinline__ void ldsm4t(unsigned* r, uint32_t a) {
    asm volatile("ldmatrix.sync.aligned.m8n8.x4.trans.shared.b16 {%0,%1,%2,%3}, [%4];"
                 : "=r"(r[0]), "=r"(r[1]), "=r"(r[2]), "=r"(r[3]) : "r"(a));
}

// ---------------- fused prep: zero counters + zero output + convert weights ----------------
__global__ void k_prep(const float* __restrict__ W1, const float* __restrict__ W2,
                       float* __restrict__ out) {
    if (blockIdx.x == 0 && threadIdx.x < NE) g_cnt[threadIdx.x] = 0;
    int tid0 = blockIdx.x * blockDim.x + threadIdx.x;
    int stride = gridDim.x * blockDim.x;
    {
        float4* o = (float4*)out;
        const int no4 = NTOK * HID / 4;
        for (int i = tid0; i < no4; i += stride)
            o[i] = make_float4(0.f, 0.f, 0.f, 0.f);
    }
    const int n4 = NE * HID * FFN / 4;
    __half2* d1 = (__half2*)g_W1h;
    __half2* d2 = (__half2*)g_W2h;
    const float4* s1 = (const float4*)W1;
    const float4* s2 = (const float4*)W2;
    for (int i = tid0; i < n4; i += stride) {
        float4 v = s1[i];
        d1[2 * i]     = __floats2half2_rn(v.x, v.y);
        d1[2 * i + 1] = __floats2half2_rn(v.z, v.w);
        float4 u = s2[i];
        d2[2 * i]     = __floats2half2_rn(u.x, u.y);
        d2[2 * i + 1] = __floats2half2_rn(u.z, u.w);
    }
}

// ---------------- router: top-2 + pairwise softmax + direct fixed-segment placement ----------------
__global__ void k_router(const float* __restrict__ x, const float* __restrict__ Wr) {
    int warp = threadIdx.x >> 5, lane = threadIdx.x & 31;
    int t = blockIdx.x * 8 + warp;
    const float* xr = x + (size_t)t * HID;
    float acc[NE];
#pragma unroll
    for (int e = 0; e < NE; e++) acc[e] = 0.f;
    for (int i = lane; i < HID; i += 32) {
        float xv = xr[i];
        const float4* w = (const float4*)(Wr + (size_t)i * NE);
        float4 w0 = w[0], w1 = w[1];
        acc[0] += xv * w0.x; acc[1] += xv * w0.y; acc[2] += xv * w0.z; acc[3] += xv * w0.w;
        acc[4] += xv * w1.x; acc[5] += xv * w1.y; acc[6] += xv * w1.z; acc[7] += xv * w1.w;
    }
#pragma unroll
    for (int e = 0; e < NE; e++)
#pragma unroll
        for (int s = 16; s > 0; s >>= 1) acc[e] += __shfl_xor_sync(0xffffffffu, acc[e], s);
    if (lane == 0) {
        int i0 = 0; float m0 = acc[0];
#pragma unroll
        for (int e = 1; e < NE; e++) if (acc[e] > m0) { m0 = acc[e]; i0 = e; }
        int i1 = -1; float m1 = -1e30f;
#pragma unroll
        for (int e = 0; e < NE; e++) if (e != i0 && acc[e] > m1) { m1 = acc[e]; i1 = e; }
        float w0 = 1.f / (1.f + expf(m1 - m0));
        int r0 = i0 * ECAP + atomicAdd(&g_cnt[i0], 1);
        g_rowTok[r0] = t; g_rowW[r0] = w0;
        int r1 = i1 * ECAP + atomicAdd(&g_cnt[i1], 1);
        g_rowTok[r1] = t; g_rowW[r1] = 1.f - w0;
    }
}

// gather + fp16-convert x into g_Xh; zero pad rows up to the 128 boundary
__global__ void k_gather(const float* __restrict__ x) {
    int r = blockIdx.x;
    int e = r / ECAP;
    int rl = r - e * ECAP;
    int c = g_cnt[e];
    __half2* dst = (__half2*)(g_Xh + (size_t)r * HID);
    int i = threadIdx.x;  // 256 threads * 4 floats
    if (rl < c) {
        const float4* src = (const float4*)(x + (size_t)g_rowTok[r] * HID);
        float4 v = src[i];
        dst[2 * i]     = __floats2half2_rn(v.x, v.y);
        dst[2 * i + 1] = __floats2half2_rn(v.z, v.w);
    } else if (rl < ((c + 127) & ~127)) {
        dst[2 * i]     = __floats2half2_rn(0.f, 0.f);
        dst[2 * i + 1] = __floats2half2_rn(0.f, 0.f);
    }
}

// ---------------- pipelined FP16 mma.sync grouped GEMM ----------------
// CTA 128x128, 8 warps (2x4) of 64x32, BK=32, 4-stage cp.async, 2 CTAs/SM
// (16 warps/SM = 4/SMSP for latency hiding; acc = 64 regs/thread).
template <int KD, int ND, bool DOGELU>
__global__ void __launch_bounds__(THREADS, 2)
k_hgemm(const float* __restrict__ Bias, float* __restrict__ Out) {
    extern __shared__ char smem[];

    int row0 = blockIdx.y * BM;
    int e = row0 / ECAP;
    int rl0 = row0 - e * ECAP;
    int cnt = g_cnt[e];
    if (rl0 >= cnt) return;
    int rend = e * ECAP + cnt;
    int nblk = blockIdx.x * BN;

    const __half* A = DOGELU ? g_Xh : g_Hh;
    const __half* B = (DOGELU ? g_W1h : g_W2h) + (size_t)e * KD * ND;

    int tid = threadIdx.x;
    uint32_t sb = smem_u32(smem);

    // cp.async slots (256 threads): A = 128 rows x 4 chunks; B = 32 k-rows x 16 chunks
    const __half* aS[2]; uint32_t aD[2];
    const __half* bS[2]; uint32_t bD[2];
#pragma unroll
    for (int p = 0; p < 2; p++) {
        int i = tid + THREADS * p;
        int r = i >> 2, j = i & 3;
        aS[p] = A + (size_t)(row0 + r) * KD + j * 8;
        aD[p] = sb + r * (APAD * 2) + j * 16;
    }
#pragma unroll
    for (int p = 0; p < 2; p++) {
        int i = tid + THREADS * p;
        int kr = i >> 4, j = i & 15;
        bS[p] = B + (size_t)kr * ND + nblk + j * 8;
        bD[p] = sb + ABYTES + kr * (BPAD * 2) + j * 16;
    }

    const int NKT = KD / BK;

    auto LOAD = [&](int kt) {
        uint32_t st = (kt % STAGES) * STGB;
        size_t ka = (size_t)kt * BK;
        size_t kb = (size_t)kt * BK * ND;
#pragma unroll
        for (int p = 0; p < 2; p++) cpa16(aD[p] + st, aS[p] + ka);
#pragma unroll
        for (int p = 0; p < 2; p++) cpa16(bD[p] + st, bS[p] + kb);
        asm volatile("cp.async.commit_group;" ::: "memory");
    };

    LOAD(0); LOAD(1); LOAD(2);

    float acc[4][4][4];
#pragma unroll
    for (int mi = 0; mi < 4; mi++)
#pragma unroll
        for (int ni = 0; ni < 4; ni++)
#pragma unroll
            for (int q = 0; q < 4; q++) acc[mi][ni][q] = 0.f;

    int wid = tid >> 5, lane = tid & 31;
    int g = lane >> 2, tg = lane & 3;
    int wm = (wid >> 2) * 64, wn = (wid & 3) * 32;
    int lane8 = lane & 7, laneb = (lane >> 3) & 1, laneh = lane >> 4;

    uint32_t aAddr0 = sb + ((wm + lane8 + laneb * 8) * APAD + laneh * 8) * 2;
    uint32_t bAddr0 = sb + ABYTES + ((lane8 + laneb * 8) * BPAD + wn + laneh * 8) * 2;

    for (int kt = 0; kt < NKT; kt++) {
        asm volatile("cp.async.wait_group %0;" :: "n"(STAGES - 2));
        __syncthreads();
        if (kt + STAGES - 1 < NKT) LOAD(kt + STAGES - 1);
        else asm volatile("cp.async.commit_group;" ::: "memory");

        uint32_t st = (kt % STAGES) * STGB;
#pragma unroll
        for (int ks = 0; ks < BK; ks += 16) {
            unsigned af[4][4], bf[4][2];
#pragma unroll
            for (int mi = 0; mi < 4; mi++)
                ldsm4(af[mi], aAddr0 + st + (mi * 16 * APAD + ks) * 2);
#pragma unroll
            for (int np = 0; np < 2; np++) {
                unsigned r[4];
                ldsm4t(r, bAddr0 + st + (ks * BPAD + np * 16) * 2);
                bf[2 * np][0] = r[0]; bf[2 * np][1] = r[1];
                bf[2 * np + 1][0] = r[2]; bf[2 * np + 1][1] = r[3];
            }
#pragma unroll
            for (int mi = 0; mi < 4; mi++)
#pragma unroll
                for (int ni = 0; ni < 4; ni++) {
                    asm volatile(
                        "mma.sync.aligned.m16n8k16.row.col.f32.f16.f16.f32 "
                        "{%0,%1,%2,%3}, {%4,%5,%6,%7}, {%8,%9}, {%0,%1,%2,%3};\n"
                        : "+f"(acc[mi][ni][0]), "+f"(acc[mi][ni][1]),
                          "+f"(acc[mi][ni][2]), "+f"(acc[mi][ni][3])
                        : "r"(af[mi][0]), "r"(af[mi][1]), "r"(af[mi][2]), "r"(af[mi][3]),
                          "r"(bf[ni][0]), "r"(bf[ni][1]));
                }
        }
    }

    asm volatile("cp.async.wait_group 0;" ::: "memory");

    // epilogue
    const float* bias = Bias + (size_t)e * ND + nblk;
    float bv[8];
#pragma unroll
    for (int ni = 0; ni < 4; ni++) {
        bv[2 * ni]     = bias[wn + ni * 8 + 2 * tg];
        bv[2 * ni + 1] = bias[wn + ni * 8 + 2 * tg + 1];
    }
#pragma unroll
    for (int mi = 0; mi < 4; mi++) {
        int rr = row0 + wm + mi * 16 + g;
        if (DOGELU) {
#pragma unroll
            for (int ni = 0; ni < 4; ni++) {
                float v0 = acc[mi][ni][0] + bv[2 * ni];
                float v1 = acc[mi][ni][1] + bv[2 * ni + 1];
                float v2 = acc[mi][ni][2] + bv[2 * ni];
                float v3 = acc[mi][ni][3] + bv[2 * ni + 1];
                v0 = 0.5f * v0 * (1.f + erff(v0 * 0.70710678118654752f));
                v1 = 0.5f * v1 * (1.f + erff(v1 * 0.70710678118654752f));
                v2 = 0.5f * v2 * (1.f + erff(v2 * 0.70710678118654752f));
                v3 = 0.5f * v3 * (1.f + erff(v3 * 0.70710678118654752f));
                int nc = wn + ni * 8 + 2 * tg;
                __half2* h0 = (__half2*)(g_Hh + (size_t)rr * ND + nblk + nc);
                __half2* h1 = (__half2*)(g_Hh + (size_t)(rr + 8) * ND + nblk + nc);
                *h0 = __floats2half2_rn(v0, v1);
                *h1 = __floats2half2_rn(v2, v3);
            }
        } else {
            bool ok0 = rr < rend, ok1 = (rr + 8) < rend;
            int   tk0 = ok0 ? g_rowTok[rr] : 0;
            int   tk1 = ok1 ? g_rowTok[rr + 8] : 0;
            float w0r = ok0 ? g_rowW[rr] : 0.f;
            float w1r = ok1 ? g_rowW[rr + 8] : 0.f;
            float* o0 = Out + (size_t)tk0 * ND + nblk;
            float* o1 = Out + (size_t)tk1 * ND + nblk;
#pragma unroll
            for (int ni = 0; ni < 4; ni++) {
                int nc = wn + ni * 8 + 2 * tg;
                if (ok0) {
                    atomicAdd(o0 + nc,     w0r * (acc[mi][ni][0] + bv[2 * ni]));
                    atomicAdd(o0 + nc + 1, w0r * (acc[mi][ni][1] + bv[2 * ni + 1]));
                }
                if (ok1) {
                    atomicAdd(o1 + nc,     w1r * (acc[mi][ni][2] + bv[2 * ni]));
                    atomicAdd(o1 + nc + 1, w1r * (acc[mi][ni][3] + bv[2 * ni + 1]));
                }
            }
        }
    }
}

// ---------------- launch ----------------
extern "C" void kernel_launch(void* const* d_in, const int* in_sizes, int n_in,
                              void* d_out, int out_size) {
    const float* x  = (const float*)d_in[0];
    const float* Wr = (const float*)d_in[1];
    const float* W1 = (const float*)d_in[2];
    const float* b1 = (const float*)d_in[3];
    const float* W2 = (const float*)d_in[4];
    const float* b2 = (const float*)d_in[5];
    float* out = (float*)d_out;

    cudaFuncSetAttribute((const void*)k_hgemm<HID, FFN, true>,
                         cudaFuncAttributeMaxDynamicSharedMemorySize, SMEM_TOTAL);
    cudaFuncSetAttribute((const void*)k_hgemm<FFN, HID, false>,
                         cudaFuncAttributeMaxDynamicSharedMemorySize, SMEM_TOTAL);

    k_prep<<<2048, 256>>>(W1, W2, out);
    k_router<<<NTOK / 8, 256>>>(x, Wr);
    k_gather<<<CAPR, 256>>>(x);

    k_hgemm<HID, FFN, true><<<dim3(FFN / BN, CAPR / BM), THREADS, SMEM_TOTAL>>>(b1, nullptr);
    k_hgemm<FFN, HID, false><<<dim3(HID / BN, CAPR / BM), THREADS, SMEM_TOTAL>>>(b2, out);
}

// round 14
// speedup vs baseline: 1.0627x; 1.0627x over previous
#include <cuda_runtime.h>
#include <cuda_fp16.h>
#include <math.h>
#include <stdint.h>

#define HID  1024
#define FFN  4096
#define NE   8
#define NTOK 4096
#define ECAP 1536                      // fixed rows per expert segment (18-sigma safe)
#define CAPR (NE * ECAP)               // 12288 total rows

#define BM 128
#define BN 128
#define BK 64
#define STAGES 3
#define APAD 72                        // halves per A smem row (144 B, conflict-free)
#define BPAD 136                       // halves per B smem k-row (272 B, conflict-free LDSM)
#define ABYTES (BM * APAD * 2)         // 18432
#define BBYTES (BK * BPAD * 2)         // 17408
#define STGB   (ABYTES + BBYTES)       // 35840
#define SMEM_TOTAL (STAGES * STGB)     // 107520 -> 2 CTAs/SM (215 KB)

// ---------------- scratch (device globals; zero-initialized at load) ----------------
__device__ int    g_cnt[NE];
__device__ int    g_rowTok[CAPR];
__device__ float  g_rowW[CAPR];
__device__ __half g_Xh[(size_t)CAPR * HID];
__device__ __half g_Hh[(size_t)CAPR * FFN];
__device__ __half g_W1h[(size_t)NE * HID * FFN];
__device__ __half g_W2h[(size_t)NE * FFN * HID];

// ---------------- helpers ----------------
__device__ __forceinline__ uint32_t smem_u32(const void* p) {
    uint32_t a;
    asm("{ .reg .u64 t; cvta.to.shared.u64 t, %1; cvt.u32.u64 %0, t; }" : "=r"(a) : "l"(p));
    return a;
}
__device__ __forceinline__ void cpa16(uint32_t s, const void* g) {
    asm volatile("cp.async.cg.shared.global [%0], [%1], 16;\n" :: "r"(s), "l"(g));
}
__device__ __forceinline__ void ldsm4(unsigned* r, uint32_t a) {
    asm volatile("ldmatrix.sync.aligned.m8n8.x4.shared.b16 {%0,%1,%2,%3}, [%4];"
                 : "=r"(r[0]), "=r"(r[1]), "=r"(r[2]), "=r"(r[3]) : "r"(a));
}
__device__ __forceinline__ void ldsm4t(unsigned* r, uint32_t a) {
    asm volatile("ldmatrix.sync.aligned.m8n8.x4.trans.shared.b16 {%0,%1,%2,%3}, [%4];"
                 : "=r"(r[0]), "=r"(r[1]), "=r"(r[2]), "=r"(r[3]) : "r"(a));
}

// ---------------- fused prep: zero counters + zero output + convert weights ----------------
__global__ void k_prep(const float* __restrict__ W1, const float* __restrict__ W2,
                       float* __restrict__ out) {
    if (blockIdx.x == 0 && threadIdx.x < NE) g_cnt[threadIdx.x] = 0;
    int tid0 = blockIdx.x * blockDim.x + threadIdx.x;
    int stride = gridDim.x * blockDim.x;
    {
        float4* o = (float4*)out;
        const int no4 = NTOK * HID / 4;
        for (int i = tid0; i < no4; i += stride)
            o[i] = make_float4(0.f, 0.f, 0.f, 0.f);
    }
    const int n4 = NE * HID * FFN / 4;
    __half2* d1 = (__half2*)g_W1h;
    __half2* d2 = (__half2*)g_W2h;
    const float4* s1 = (const float4*)W1;
    const float4* s2 = (const float4*)W2;
    for (int i = tid0; i < n4; i += stride) {
        float4 v = s1[i];
        d1[2 * i]     = __floats2half2_rn(v.x, v.y);
        d1[2 * i + 1] = __floats2half2_rn(v.z, v.w);
        float4 u = s2[i];
        d2[2 * i]     = __floats2half2_rn(u.x, u.y);
        d2[2 * i + 1] = __floats2half2_rn(u.z, u.w);
    }
}

// ---------------- router: top-2 + pairwise softmax + direct fixed-segment placement ----------------
__global__ void k_router(const float* __restrict__ x, const float* __restrict__ Wr) {
    int warp = threadIdx.x >> 5, lane = threadIdx.x & 31;
    int t = blockIdx.x * 8 + warp;
    const float* xr = x + (size_t)t * HID;
    float acc[NE];
#pragma unroll
    for (int e = 0; e < NE; e++) acc[e] = 0.f;
    for (int i = lane; i < HID; i += 32) {
        float xv = xr[i];
        const float4* w = (const float4*)(Wr + (size_t)i * NE);
        float4 w0 = w[0], w1 = w[1];
        acc[0] += xv * w0.x; acc[1] += xv * w0.y; acc[2] += xv * w0.z; acc[3] += xv * w0.w;
        acc[4] += xv * w1.x; acc[5] += xv * w1.y; acc[6] += xv * w1.z; acc[7] += xv * w1.w;
    }
#pragma unroll
    for (int e = 0; e < NE; e++)
#pragma unroll
        for (int s = 16; s > 0; s >>= 1) acc[e] += __shfl_xor_sync(0xffffffffu, acc[e], s);
    if (lane == 0) {
        int i0 = 0; float m0 = acc[0];
#pragma unroll
        for (int e = 1; e < NE; e++) if (acc[e] > m0) { m0 = acc[e]; i0 = e; }
        int i1 = -1; float m1 = -1e30f;
#pragma unroll
        for (int e = 0; e < NE; e++) if (e != i0 && acc[e] > m1) { m1 = acc[e]; i1 = e; }
        float w0 = 1.f / (1.f + expf(m1 - m0));
        int r0 = i0 * ECAP + atomicAdd(&g_cnt[i0], 1);
        g_rowTok[r0] = t; g_rowW[r0] = w0;
        int r1 = i1 * ECAP + atomicAdd(&g_cnt[i1], 1);
        g_rowTok[r1] = t; g_rowW[r1] = 1.f - w0;
    }
}

// gather + fp16-convert x into g_Xh; zero pad rows up to the 128 boundary
__global__ void k_gather(const float* __restrict__ x) {
    int r = blockIdx.x;
    int e = r / ECAP;
    int rl = r - e * ECAP;
    int c = g_cnt[e];
    __half2* dst = (__half2*)(g_Xh + (size_t)r * HID);
    int i = threadIdx.x;  // 256 threads * 4 floats
    if (rl < c) {
        const float4* src = (const float4*)(x + (size_t)g_rowTok[r] * HID);
        float4 v = src[i];
        dst[2 * i]     = __floats2half2_rn(v.x, v.y);
        dst[2 * i + 1] = __floats2half2_rn(v.z, v.w);
    } else if (rl < ((c + 127) & ~127)) {
        dst[2 * i]     = __floats2half2_rn(0.f, 0.f);
        dst[2 * i + 1] = __floats2half2_rn(0.f, 0.f);
    }
}

// ---------------- pipelined FP16 mma.sync grouped GEMM ----------------
// CTA 128x128, 4 warps (2x2) of 64x64, BK=64, 3-stage cp.async, 2 CTAs/SM.
template <int KD, int ND, bool DOGELU>
__global__ void __launch_bounds__(128, 2)
k_hgemm(const float* __restrict__ Bias, float* __restrict__ Out) {
    extern __shared__ char smem[];

    int row0 = blockIdx.y * BM;
    int e = row0 / ECAP;
    int rl0 = row0 - e * ECAP;
    int cnt = g_cnt[e];
    if (rl0 >= cnt) return;
    int rend = e * ECAP + cnt;
    int nblk = blockIdx.x * BN;

    const __half* A = DOGELU ? g_Xh : g_Hh;
    const __half* B = (DOGELU ? g_W1h : g_W2h) + (size_t)e * KD * ND;

    int tid = threadIdx.x;
    uint32_t sb = smem_u32(smem);

    // cp.async slots: A = 128 rows x 8 chunks(16B=8 halves); B = 64 k-rows x 16 chunks
    const __half* aS[8]; uint32_t aD[8];
    const __half* bS[8]; uint32_t bD[8];
#pragma unroll
    for (int p = 0; p < 8; p++) {
        int i = tid + 128 * p;
        int r = i >> 3, j = i & 7;
        aS[p] = A + (size_t)(row0 + r) * KD + j * 8;
        aD[p] = sb + r * (APAD * 2) + j * 16;
    }
#pragma unroll
    for (int p = 0; p < 8; p++) {
        int i = tid + 128 * p;
        int kr = i >> 4, j = i & 15;
        bS[p] = B + (size_t)kr * ND + nblk + j * 8;
        bD[p] = sb + ABYTES + kr * (BPAD * 2) + j * 16;
    }

    const int NKT = KD / BK;

    auto LOAD = [&](int kt) {
        uint32_t st = (kt % STAGES) * STGB;
        size_t ka = (size_t)kt * BK;
        size_t kb = (size_t)kt * BK * ND;
#pragma unroll
        for (int p = 0; p < 8; p++) cpa16(aD[p] + st, aS[p] + ka);
#pragma unroll
        for (int p = 0; p < 8; p++) cpa16(bD[p] + st, bS[p] + kb);
        asm volatile("cp.async.commit_group;" ::: "memory");
    };

    LOAD(0); LOAD(1);

    float acc[4][8][4];
#pragma unroll
    for (int mi = 0; mi < 4; mi++)
#pragma unroll
        for (int ni = 0; ni < 8; ni++)
#pragma unroll
            for (int q = 0; q < 4; q++) acc[mi][ni][q] = 0.f;

    int wid = tid >> 5, lane = tid & 31;
    int g = lane >> 2, tg = lane & 3;
    int wm = (wid >> 1) * 64, wn = (wid & 1) * 64;
    int lane8 = lane & 7, laneb = (lane >> 3) & 1, laneh = lane >> 4;

    uint32_t aAddr0 = sb + ((wm + lane8 + laneb * 8) * APAD + laneh * 8) * 2;
    uint32_t bAddr0 = sb + ABYTES + ((lane8 + laneb * 8) * BPAD + wn + laneh * 8) * 2;

    for (int kt = 0; kt < NKT; kt++) {
        asm volatile("cp.async.wait_group %0;" :: "n"(STAGES - 2));
        __syncthreads();
        if (kt + STAGES - 1 < NKT) LOAD(kt + STAGES - 1);
        else asm volatile("cp.async.commit_group;" ::: "memory");

        uint32_t st = (kt % STAGES) * STGB;
#pragma unroll
        for (int ks = 0; ks < BK; ks += 16) {
            unsigned af[4][4], bf[8][2];
#pragma unroll
            for (int mi = 0; mi < 4; mi++)
                ldsm4(af[mi], aAddr0 + st + (mi * 16 * APAD + ks) * 2);
#pragma unroll
            for (int np = 0; np < 4; np++) {
                unsigned r[4];
                ldsm4t(r, bAddr0 + st + (ks * BPAD + np * 16) * 2);
                bf[2 * np][0] = r[0]; bf[2 * np][1] = r[1];
                bf[2 * np + 1][0] = r[2]; bf[2 * np + 1][1] = r[3];
            }
#pragma unroll
            for (int mi = 0; mi < 4; mi++)
#pragma unroll
                for (int ni = 0; ni < 8; ni++) {
                    asm volatile(
                        "mma.sync.aligned.m16n8k16.row.col.f32.f16.f16.f32 "
                        "{%0,%1,%2,%3}, {%4,%5,%6,%7}, {%8,%9}, {%0,%1,%2,%3};\n"
                        : "+f"(acc[mi][ni][0]), "+f"(acc[mi][ni][1]),
                          "+f"(acc[mi][ni][2]), "+f"(acc[mi][ni][3])
                        : "r"(af[mi][0]), "r"(af[mi][1]), "r"(af[mi][2]), "r"(af[mi][3]),
                          "r"(bf[ni][0]), "r"(bf[ni][1]));
                }
        }
    }

    asm volatile("cp.async.wait_group 0;" ::: "memory");

    // epilogue
    const float* bias = Bias + (size_t)e * ND + nblk;
    float bv[16];
#pragma unroll
    for (int ni = 0; ni < 8; ni++) {
        bv[2 * ni]     = bias[wn + ni * 8 + 2 * tg];
        bv[2 * ni + 1] = bias[wn + ni * 8 + 2 * tg + 1];
    }
#pragma unroll
    for (int mi = 0; mi < 4; mi++) {
        int rr = row0 + wm + mi * 16 + g;
        if (DOGELU) {
#pragma unroll
            for (int ni = 0; ni < 8; ni++) {
                float v0 = acc[mi][ni][0] + bv[2 * ni];
                float v1 = acc[mi][ni][1] + bv[2 * ni + 1];
                float v2 = acc[mi][ni][2] + bv[2 * ni];
                float v3 = acc[mi][ni][3] + bv[2 * ni + 1];
                v0 = 0.5f * v0 * (1.f + erff(v0 * 0.70710678118654752f));
                v1 = 0.5f * v1 * (1.f + erff(v1 * 0.70710678118654752f));
                v2 = 0.5f * v2 * (1.f + erff(v2 * 0.70710678118654752f));
                v3 = 0.5f * v3 * (1.f + erff(v3 * 0.70710678118654752f));
                int nc = wn + ni * 8 + 2 * tg;
                __half2* h0 = (__half2*)(g_Hh + (size_t)rr * ND + nblk + nc);
                __half2* h1 = (__half2*)(g_Hh + (size_t)(rr + 8) * ND + nblk + nc);
                *h0 = __floats2half2_rn(v0, v1);
                *h1 = __floats2half2_rn(v2, v3);
            }
        } else {
            bool ok0 = rr < rend, ok1 = (rr + 8) < rend;
            int   tk0 = ok0 ? g_rowTok[rr] : 0;
            int   tk1 = ok1 ? g_rowTok[rr + 8] : 0;
            float w0r = ok0 ? g_rowW[rr] : 0.f;
            float w1r = ok1 ? g_rowW[rr + 8] : 0.f;
            float* o0 = Out + (size_t)tk0 * ND + nblk;
            float* o1 = Out + (size_t)tk1 * ND + nblk;
#pragma unroll
            for (int ni = 0; ni < 8; ni++) {
                int nc = wn + ni * 8 + 2 * tg;
                if (ok0) {
                    atomicAdd(o0 + nc,     w0r * (acc[mi][ni][0] + bv[2 * ni]));
                    atomicAdd(o0 + nc + 1, w0r * (acc[mi][ni][1] + bv[2 * ni + 1]));
                }
                if (ok1) {
                    atomicAdd(o1 + nc,     w1r * (acc[mi][ni][2] + bv[2 * ni]));
                    atomicAdd(o1 + nc + 1, w1r * (acc[mi][ni][3] + bv[2 * ni + 1]));
                }
            }
        }
    }
}

// ---------------- launch ----------------
extern "C" void kernel_launch(void* const* d_in, const int* in_sizes, int n_in,
                              void* d_out, int out_size) {
    const float* x  = (const float*)d_in[0];
    const float* Wr = (const float*)d_in[1];
    const float* W1 = (const float*)d_in[2];
    const float* b1 = (const float*)d_in[3];
    const float* W2 = (const float*)d_in[4];
    const float* b2 = (const float*)d_in[5];
    float* out = (float*)d_out;

    cudaFuncSetAttribute((const void*)k_hgemm<HID, FFN, true>,
                         cudaFuncAttributeMaxDynamicSharedMemorySize, SMEM_TOTAL);
    cudaFuncSetAttribute((const void*)k_hgemm<FFN, HID, false>,
                         cudaFuncAttributeMaxDynamicSharedMemorySize, SMEM_TOTAL);

    k_prep<<<2048, 256>>>(W1, W2, out);
    k_router<<<NTOK / 8, 256>>>(x, Wr);
    k_gather<<<CAPR, 256>>>(x);

    k_hgemm<HID, FFN, true><<<dim3(FFN / BN, CAPR / BM), 128, SMEM_TOTAL>>>(b1, nullptr);
    k_hgemm<FFN, HID, false><<<dim3(HID / BN, CAPR / BM), 128, SMEM_TOTAL>>>(b2, out);
}

// round 15
// speedup vs baseline: 1.1554x; 1.0872x over previous
#include <cuda_runtime.h>
#include <cuda_fp16.h>
#include <math.h>
#include <stdint.h>

#define HID  1024
#define FFN  4096
#define NE   8
#define NTOK 4096
#define ECAP 1280                      // fixed rows per expert segment (9-sigma safe)
#define CAPR (NE * ECAP)               // 10240 total rows

#define BM 128
#define BN 128
#define BK 32
#define STAGES 4
#define APAD 40                        // halves per A smem row (80 B, conflict-free LDSM)
#define BPAD 136                       // halves per B smem k-row (272 B, conflict-free LDSM)
#define ABYTES (BM * APAD * 2)         // 10240
#define BBYTES (BK * BPAD * 2)         // 8704
#define STGB   (ABYTES + BBYTES)       // 18944
#define SMEM_TOTAL (STAGES * STGB)     // 75776 -> 2 CTAs/SM

// ---------------- scratch (device globals; zero-initialized at load) ----------------
__device__ int    g_cnt[NE];
__device__ int    g_rowTok[CAPR];
__device__ float  g_rowW[CAPR];
__device__ __half g_Xh[(size_t)CAPR * HID];
__device__ __half g_Hh[(size_t)CAPR * FFN];
__device__ __half g_W1h[(size_t)NE * HID * FFN];
__device__ __half g_W2h[(size_t)NE * FFN * HID];

// ---------------- helpers ----------------
__device__ __forceinline__ uint32_t smem_u32(const void* p) {
    uint32_t a;
    asm("{ .reg .u64 t; cvta.to.shared.u64 t, %1; cvt.u32.u64 %0, t; }" : "=r"(a) : "l"(p));
    return a;
}
__device__ __forceinline__ void cpa16(uint32_t s, const void* g) {
    asm volatile("cp.async.cg.shared.global [%0], [%1], 16;\n" :: "r"(s), "l"(g));
}
__device__ __forceinline__ void ldsm4(unsigned* r, uint32_t a) {
    asm volatile("ldmatrix.sync.aligned.m8n8.x4.shared.b16 {%0,%1,%2,%3}, [%4];"
                 : "=r"(r[0]), "=r"(r[1]), "=r"(r[2]), "=r"(r[3]) : "r"(a));
}
__device__ __forceinline__ void ldsm4t(unsigned* r, uint32_t a) {
    asm volatile("ldmatrix.sync.aligned.m8n8.x4.trans.shared.b16 {%0,%1,%2,%3}, [%4];"
                 : "=r"(r[0]), "=r"(r[1]), "=r"(r[2]), "=r"(r[3]) : "r"(a));
}

// ---------------- fused prep: zero counters + zero output + convert weights ----------------
__global__ void k_prep(const float* __restrict__ W1, const float* __restrict__ W2,
                       float* __restrict__ out) {
    if (blockIdx.x == 0 && threadIdx.x < NE) g_cnt[threadIdx.x] = 0;
    int tid0 = blockIdx.x * blockDim.x + threadIdx.x;
    int stride = gridDim.x * blockDim.x;
    {
        float4* o = (float4*)out;
        const int no4 = NTOK * HID / 4;
        for (int i = tid0; i < no4; i += stride)
            o[i] = make_float4(0.f, 0.f, 0.f, 0.f);
    }
    const int n4 = NE * HID * FFN / 4;
    __half2* d1 = (__half2*)g_W1h;
    __half2* d2 = (__half2*)g_W2h;
    const float4* s1 = (const float4*)W1;
    const float4* s2 = (const float4*)W2;
    for (int i = tid0; i < n4; i += stride) {
        float4 v = s1[i];
        d1[2 * i]     = __floats2half2_rn(v.x, v.y);
        d1[2 * i + 1] = __floats2half2_rn(v.z, v.w);
        float4 u = s2[i];
        d2[2 * i]     = __floats2half2_rn(u.x, u.y);
        d2[2 * i + 1] = __floats2half2_rn(u.z, u.w);
    }
}

// ---------------- router: top-2 + pairwise softmax + direct fixed-segment placement ----------------
__global__ void k_router(const float* __restrict__ x, const float* __restrict__ Wr) {
    int warp = threadIdx.x >> 5, lane = threadIdx.x & 31;
    int t = blockIdx.x * 8 + warp;
    const float* xr = x + (size_t)t * HID;
    float acc[NE];
#pragma unroll
    for (int e = 0; e < NE; e++) acc[e] = 0.f;
    for (int i = lane; i < HID; i += 32) {
        float xv = xr[i];
        const float4* w = (const float4*)(Wr + (size_t)i * NE);
        float4 w0 = w[0], w1 = w[1];
        acc[0] += xv * w0.x; acc[1] += xv * w0.y; acc[2] += xv * w0.z; acc[3] += xv * w0.w;
        acc[4] += xv * w1.x; acc[5] += xv * w1.y; acc[6] += xv * w1.z; acc[7] += xv * w1.w;
    }
#pragma unroll
    for (int e = 0; e < NE; e++)
#pragma unroll
        for (int s = 16; s > 0; s >>= 1) acc[e] += __shfl_xor_sync(0xffffffffu, acc[e], s);
    if (lane == 0) {
        int i0 = 0; float m0 = acc[0];
#pragma unroll
        for (int e = 1; e < NE; e++) if (acc[e] > m0) { m0 = acc[e]; i0 = e; }
        int i1 = -1; float m1 = -1e30f;
#pragma unroll
        for (int e = 0; e < NE; e++) if (e != i0 && acc[e] > m1) { m1 = acc[e]; i1 = e; }
        float w0 = 1.f / (1.f + expf(m1 - m0));
        int r0 = i0 * ECAP + atomicAdd(&g_cnt[i0], 1);
        g_rowTok[r0] = t; g_rowW[r0] = w0;
        int r1 = i1 * ECAP + atomicAdd(&g_cnt[i1], 1);
        g_rowTok[r1] = t; g_rowW[r1] = 1.f - w0;
    }
}

// gather + fp16-convert x into g_Xh; zero pad rows up to the 128 boundary
__global__ void k_gather(const float* __restrict__ x) {
    int r = blockIdx.x;
    int e = r / ECAP;
    int rl = r - e * ECAP;
    int c = g_cnt[e];
    __half2* dst = (__half2*)(g_Xh + (size_t)r * HID);
    int i = threadIdx.x;  // 256 threads * 4 floats
    if (rl < c) {
        const float4* src = (const float4*)(x + (size_t)g_rowTok[r] * HID);
        float4 v = src[i];
        dst[2 * i]     = __floats2half2_rn(v.x, v.y);
        dst[2 * i + 1] = __floats2half2_rn(v.z, v.w);
    } else if (rl < ((c + 127) & ~127)) {
        dst[2 * i]     = __floats2half2_rn(0.f, 0.f);
        dst[2 * i + 1] = __floats2half2_rn(0.f, 0.f);
    }
}

// ---------------- pipelined FP16 mma.sync grouped GEMM ----------------
// CTA 128x128, 4 warps (2x2) of 64x64, BK=32, 4-stage cp.async, 2 CTAs/SM.
// Fragment software-pipelining: all 16 LDSM for both ks-halves issued before
// the 64 MMAs, so the second half's LDSM latency hides under the first's MMAs.
template <int KD, int ND, bool DOGELU>
__global__ void __launch_bounds__(128, 2)
k_hgemm(const float* __restrict__ Bias, float* __restrict__ Out) {
    extern __shared__ char smem[];

    int row0 = blockIdx.y * BM;
    int e = row0 / ECAP;
    int rl0 = row0 - e * ECAP;
    int cnt = g_cnt[e];
    if (rl0 >= cnt) return;
    int rend = e * ECAP + cnt;
    int nblk = blockIdx.x * BN;

    const __half* A = DOGELU ? g_Xh : g_Hh;
    const __half* B = (DOGELU ? g_W1h : g_W2h) + (size_t)e * KD * ND;

    int tid = threadIdx.x;
    uint32_t sb = smem_u32(smem);

    // cp.async slots: A = 128 rows x 4 chunks(16B=8 halves); B = 32 k-rows x 16 chunks
    const __half* aS[4]; uint32_t aD[4];
    const __half* bS[4]; uint32_t bD[4];
#pragma unroll
    for (int p = 0; p < 4; p++) {
        int i = tid + 128 * p;
        int r = i >> 2, j = i & 3;
        aS[p] = A + (size_t)(row0 + r) * KD + j * 8;
        aD[p] = sb + r * (APAD * 2) + j * 16;
    }
#pragma unroll
    for (int p = 0; p < 4; p++) {
        int i = tid + 128 * p;
        int kr = i >> 4, j = i & 15;
        bS[p] = B + (size_t)kr * ND + nblk + j * 8;
        bD[p] = sb + ABYTES + kr * (BPAD * 2) + j * 16;
    }

    const int NKT = KD / BK;

    auto LOAD = [&](int kt) {
        uint32_t st = (kt % STAGES) * STGB;
        size_t ka = (size_t)kt * BK;
        size_t kb = (size_t)kt * BK * ND;
#pragma unroll
        for (int p = 0; p < 4; p++) cpa16(aD[p] + st, aS[p] + ka);
#pragma unroll
        for (int p = 0; p < 4; p++) cpa16(bD[p] + st, bS[p] + kb);
        asm volatile("cp.async.commit_group;" ::: "memory");
    };

    LOAD(0); LOAD(1); LOAD(2);

    float acc[4][8][4];
#pragma unroll
    for (int mi = 0; mi < 4; mi++)
#pragma unroll
        for (int ni = 0; ni < 8; ni++)
#pragma unroll
            for (int q = 0; q < 4; q++) acc[mi][ni][q] = 0.f;

    int wid = tid >> 5, lane = tid & 31;
    int g = lane >> 2, tg = lane & 3;
    int wm = (wid >> 1) * 64, wn = (wid & 1) * 64;
    int lane8 = lane & 7, laneb = (lane >> 3) & 1, laneh = lane >> 4;

    uint32_t aAddr0 = sb + ((wm + lane8 + laneb * 8) * APAD + laneh * 8) * 2;
    uint32_t bAddr0 = sb + ABYTES + ((lane8 + laneb * 8) * BPAD + wn + laneh * 8) * 2;

    for (int kt = 0; kt < NKT; kt++) {
        asm volatile("cp.async.wait_group %0;" :: "n"(STAGES - 2));
        __syncthreads();
        if (kt + STAGES - 1 < NKT) LOAD(kt + STAGES - 1);
        else asm volatile("cp.async.commit_group;" ::: "memory");

        uint32_t st = (kt % STAGES) * STGB;
        unsigned af[2][4][4], bf[2][8][2];
        // issue ALL fragment loads for both ks-halves first
#pragma unroll
        for (int h = 0; h < 2; h++) {
            int ks = h * 16;
#pragma unroll
            for (int mi = 0; mi < 4; mi++)
                ldsm4(af[h][mi], aAddr0 + st + (mi * 16 * APAD + ks) * 2);
#pragma unroll
            for (int np = 0; np < 4; np++) {
                unsigned r[4];
                ldsm4t(r, bAddr0 + st + (ks * BPAD + np * 16) * 2);
                bf[h][2 * np][0] = r[0]; bf[h][2 * np][1] = r[1];
                bf[h][2 * np + 1][0] = r[2]; bf[h][2 * np + 1][1] = r[3];
            }
        }
        // then all 64 MMAs
#pragma unroll
        for (int h = 0; h < 2; h++)
#pragma unroll
            for (int mi = 0; mi < 4; mi++)
#pragma unroll
                for (int ni = 0; ni < 8; ni++) {
                    asm volatile(
                        "mma.sync.aligned.m16n8k16.row.col.f32.f16.f16.f32 "
                        "{%0,%1,%2,%3}, {%4,%5,%6,%7}, {%8,%9}, {%0,%1,%2,%3};\n"
                        : "+f"(acc[mi][ni][0]), "+f"(acc[mi][ni][1]),
                          "+f"(acc[mi][ni][2]), "+f"(acc[mi][ni][3])
                        : "r"(af[h][mi][0]), "r"(af[h][mi][1]),
                          "r"(af[h][mi][2]), "r"(af[h][mi][3]),
                          "r"(bf[h][ni][0]), "r"(bf[h][ni][1]));
                }
    }

    asm volatile("cp.async.wait_group 0;" ::: "memory");

    // epilogue
    const float* bias = Bias + (size_t)e * ND + nblk;
    float bv[16];
#pragma unroll
    for (int ni = 0; ni < 8; ni++) {
        bv[2 * ni]     = bias[wn + ni * 8 + 2 * tg];
        bv[2 * ni + 1] = bias[wn + ni * 8 + 2 * tg + 1];
    }
#pragma unroll
    for (int mi = 0; mi < 4; mi++) {
        int rr = row0 + wm + mi * 16 + g;
        if (DOGELU) {
#pragma unroll
            for (int ni = 0; ni < 8; ni++) {
                float v0 = acc[mi][ni][0] + bv[2 * ni];
                float v1 = acc[mi][ni][1] + bv[2 * ni + 1];
                float v2 = acc[mi][ni][2] + bv[2 * ni];
                float v3 = acc[mi][ni][3] + bv[2 * ni + 1];
                v0 = 0.5f * v0 * (1.f + erff(v0 * 0.70710678118654752f));
                v1 = 0.5f * v1 * (1.f + erff(v1 * 0.70710678118654752f));
                v2 = 0.5f * v2 * (1.f + erff(v2 * 0.70710678118654752f));
                v3 = 0.5f * v3 * (1.f + erff(v3 * 0.70710678118654752f));
                int nc = wn + ni * 8 + 2 * tg;
                __half2* h0 = (__half2*)(g_Hh + (size_t)rr * ND + nblk + nc);
                __half2* h1 = (__half2*)(g_Hh + (size_t)(rr + 8) * ND + nblk + nc);
                *h0 = __floats2half2_rn(v0, v1);
                *h1 = __floats2half2_rn(v2, v3);
            }
        } else {
            bool ok0 = rr < rend, ok1 = (rr + 8) < rend;
            int   tk0 = ok0 ? g_rowTok[rr] : 0;
            int   tk1 = ok1 ? g_rowTok[rr + 8] : 0;
            float w0r = ok0 ? g_rowW[rr] : 0.f;
            float w1r = ok1 ? g_rowW[rr + 8] : 0.f;
            float* o0 = Out + (size_t)tk0 * ND + nblk;
            float* o1 = Out + (size_t)tk1 * ND + nblk;
#pragma unroll
            for (int ni = 0; ni < 8; ni++) {
                int nc = wn + ni * 8 + 2 * tg;
                if (ok0) {
                    atomicAdd(o0 + nc,     w0r * (acc[mi][ni][0] + bv[2 * ni]));
                    atomicAdd(o0 + nc + 1, w0r * (acc[mi][ni][1] + bv[2 * ni + 1]));
                }
                if (ok1) {
                    atomicAdd(o1 + nc,     w1r * (acc[mi][ni][2] + bv[2 * ni]));
                    atomicAdd(o1 + nc + 1, w1r * (acc[mi][ni][3] + bv[2 * ni + 1]));
                }
            }
        }
    }
}

// ---------------- launch ----------------
extern "C" void kernel_launch(void* const* d_in, const int* in_sizes, int n_in,
                              void* d_out, int out_size) {
    const float* x  = (const float*)d_in[0];
    const float* Wr = (const float*)d_in[1];
    const float* W1 = (const float*)d_in[2];
    const float* b1 = (const float*)d_in[3];
    const float* W2 = (const float*)d_in[4];
    const float* b2 = (const float*)d_in[5];
    float* out = (float*)d_out;

    cudaFuncSetAttribute((const void*)k_hgemm<HID, FFN, true>,
                         cudaFuncAttributeMaxDynamicSharedMemorySize, SMEM_TOTAL);
    cudaFuncSetAttribute((const void*)k_hgemm<FFN, HID, false>,
                         cudaFuncAttributeMaxDynamicSharedMemorySize, SMEM_TOTAL);

    k_prep<<<2048, 256>>>(W1, W2, out);
    k_router<<<NTOK / 8, 256>>>(x, Wr);
    k_gather<<<CAPR, 256>>>(x);

    k_hgemm<HID, FFN, true><<<dim3(FFN / BN, CAPR / BM), 128, SMEM_TOTAL>>>(b1, nullptr);
    k_hgemm<FFN, HID, false><<<dim3(HID / BN, CAPR / BM), 128, SMEM_TOTAL>>>(b2, out);
}